// round 4
// baseline (speedup 1.0000x reference)
#include <cuda_runtime.h>
#include <math.h>
#include <stdint.h>

#define KC 4
#define D  8
#define NTRI 36   // lower-triangular 8x8 element count

// ln(2*pi), ln(2)
#define LOG_2PI 1.8378770664093453f
#define LN2F    0.6931471805599453f

typedef unsigned long long ull;

// ---------------------------------------------------------------------------
// f32x2 packed-math helpers (sm_100a; ptxas emits FFMA2 only via PTX)
// ---------------------------------------------------------------------------
__device__ __forceinline__ ull fma2(ull a, ull b, ull c) {
    ull d;
    asm("fma.rn.f32x2 %0, %1, %2, %3;" : "=l"(d) : "l"(a), "l"(b), "l"(c));
    return d;
}
__device__ __forceinline__ ull pack2(float lo, float hi) {
    ull d;
    asm("mov.b64 %0, {%1, %2};" : "=l"(d) : "f"(lo), "f"(hi));
    return d;
}
__device__ __forceinline__ void unpack2(ull v, float& lo, float& hi) {
    asm("mov.b64 {%0, %1}, %2;" : "=f"(lo), "=f"(hi) : "l"(v));
}
__device__ __forceinline__ float rcp_a(float x)  { float y; asm("rcp.approx.f32 %0, %1;"   : "=f"(y) : "f"(x)); return y; }
__device__ __forceinline__ float rsq_a(float x)  { float y; asm("rsqrt.approx.f32 %0, %1;" : "=f"(y) : "f"(x)); return y; }
__device__ __forceinline__ float lg2_a(float x)  { float y; asm("lg2.approx.f32 %0, %1;"   : "=f"(y) : "f"(x)); return y; }

// ---------------------------------------------------------------------------
// Precomputed parameters. Packed (l,l) pairs first (hot-path payload), then
// scalar copies for the tail path, then masks.
// ---------------------------------------------------------------------------
struct Params {
    ull   lpair[KC][NTRI];  // (Linv[r][c], Linv[r][c]) lower-tri flattened r*(r+1)/2+c
    ull   bpair[KC][D];     // (-bias[r], -bias[r])
    ull   cfpair[KC];       // (cfix, cfix)
    float Linv[KC][D][D];   // scalar copies for tail
    float bias[KC][D];
    float cfix[KC];
    int   active[KC];
    int   tmask[KC];        // one-hot bit of target component ci = indices[i]
    int   wmask[KC];        // bit j set if indices[j] != ci
    int   cnt;
    int   _pad;
};

__device__ Params g_p;
__device__ double g_sum;        // zero-init at module load; self-reset per launch
__device__ unsigned int g_ticket;

// ---------------------------------------------------------------------------
// Kernel 1: setup — one thread per component, approx-MUFU rcp/rsqrt/lg2
// (accurate div/sqrt/logf routines were the bulk of R3's 9.8us).
// ---------------------------------------------------------------------------
__global__ void setup_kernel(const float* __restrict__ means,
                             const float* __restrict__ covs,
                             const int*   __restrict__ indices)
{
    const int j = threadIdx.x;
    if (blockIdx.x != 0 || j >= KC) return;

    float L[D][D], Li[D][D];
    const float* a = covs + j * D * D;
    // Cholesky: cov = L * L^T  (approx rsqrt/rcp; cov eigmin >= 0.5)
    #pragma unroll
    for (int r = 0; r < D; ++r) {
        #pragma unroll
        for (int c = 0; c <= r; ++c) {
            float s = a[r * D + c];
            #pragma unroll
            for (int k = 0; k < c; ++k) s -= L[r][k] * L[c][k];
            if (c == r) L[r][c] = s * rsq_a(s);
            else        L[r][c] = s * rcp_a(L[c][c]);
        }
    }
    // Invert lower-triangular L; half-log-det via lg2
    float hld = 0.0f;
    #pragma unroll
    for (int c = 0; c < D; ++c) {
        Li[c][c] = rcp_a(L[c][c]);
        #pragma unroll
        for (int r = c + 1; r < D; ++r) {
            float s = 0.0f;
            #pragma unroll
            for (int k = c; k < r; ++k) s += L[r][k] * Li[k][c];
            Li[r][c] = -s * rcp_a(L[r][r]);
        }
        hld += lg2_a(L[c][c]);
    }
    hld *= LN2F;

    int t = 0;
    #pragma unroll
    for (int r = 0; r < D; ++r)
        #pragma unroll
        for (int c = 0; c <= r; ++c) {
            g_p.lpair[j][t] = pack2(Li[r][c], Li[r][c]);
            ++t;
        }
    #pragma unroll
    for (int r = 0; r < D; ++r)
        #pragma unroll
        for (int c = 0; c < D; ++c)
            g_p.Linv[j][r][c] = (c <= r) ? Li[r][c] : 0.0f;
    #pragma unroll
    for (int r = 0; r < D; ++r) {
        float s = 0.0f;
        #pragma unroll
        for (int c = 0; c <= r; ++c) s += Li[r][c] * means[j * D + c];
        g_p.bias[j][r]  = s;
        g_p.bpair[j][r] = pack2(-s, -s);
    }
    float cf = 0.5f * (float)D * LOG_2PI - hld;
    g_p.cfix[j]   = cf;
    g_p.cfpair[j] = pack2(cf, cf);

    if (j == 0) {
        int cnt = 0;
        for (int i = 0; i < KC; ++i) {
            int ci = indices[i];
            int act = (ci != 0);
            g_p.active[i] = act;
            if (act) cnt++;
            int ti = ci; if (ti < 0) ti = 0; if (ti > KC - 1) ti = KC - 1;
            g_p.tmask[i] = 1 << ti;
            int wm = 0;
            for (int jj = 0; jj < KC; ++jj)
                if (indices[jj] != ci) wm |= (1 << jj);
            g_p.wmask[i] = wm;
        }
        g_p.cnt = cnt;
    }
}

// ---------------------------------------------------------------------------
// Kernel 2: fused hot path + finalize. 4 samples/thread via f32x2 packed FMA;
// fp64 block reduction; last block (ticket) handles tail + scalar output and
// self-resets the accumulators for graph replay.
// ---------------------------------------------------------------------------
__global__ void __launch_bounds__(256) lp_kernel(const float* __restrict__ pred, int N,
                                                 float* __restrict__ out)
{
    __shared__ Params sp;
    {
        const int nq = (int)(sizeof(Params) / 8);
        const ull* src = (const ull*)&g_p;
        ull* dst = (ull*)&sp;
        for (int u = threadIdx.x; u < nq; u += blockDim.x) dst[u] = src[u];
    }
    __syncthreads();

    const int N4 = N >> 2;
    const int tid = blockIdx.x * blockDim.x + threadIdx.x;
    const int stride = gridDim.x * blockDim.x;
    const ull HALF2 = 0x3F0000003F000000ULL;  // (0.5f, 0.5f)

    float acc = 0.0f;

    for (int v = tid; v < N4; v += stride) {
        #pragma unroll
        for (int i = 0; i < KC; ++i) {
            if (!sp.active[i]) continue;
            const ulonglong2* base = (const ulonglong2*)pred + (size_t)i * D * N4;
            ull x01[D], x23[D];
            #pragma unroll
            for (int dd = 0; dd < D; ++dd) {
                ulonglong2 q = base[(size_t)dd * N4 + v];
                x01[dd] = q.x;   // samples 0,1
                x23[dd] = q.y;   // samples 2,3
            }

            ull L01[KC], L23[KC];
            #pragma unroll
            for (int j = 0; j < KC; ++j) {
                ull M01 = 0ull, M23 = 0ull;  // (+0.0f, +0.0f)
                int t = 0;
                #pragma unroll
                for (int r = 0; r < D; ++r) {
                    ull s01 = sp.bpair[j][r];
                    ull s23 = s01;
                    #pragma unroll
                    for (int c = 0; c <= r; ++c) {
                        ull l = sp.lpair[j][t]; ++t;
                        s01 = fma2(l, x01[c], s01);
                        s23 = fma2(l, x23[c], s23);
                    }
                    M01 = fma2(s01, s01, M01);
                    M23 = fma2(s23, s23, M23);
                }
                L01[j] = fma2(HALF2, M01, sp.cfpair[j]);
                L23[j] = fma2(HALF2, M23, sp.cfpair[j]);
            }

            float lp[KC][4];
            #pragma unroll
            for (int j = 0; j < KC; ++j) {
                unpack2(L01[j], lp[j][0], lp[j][1]);
                unpack2(L23[j], lp[j][2], lp[j][3]);
            }

            const int tm = sp.tmask[i];
            const int wm = sp.wmask[i];
            #pragma unroll
            for (int s = 0; s < 4; ++s) {
                float e0 = __expf(lp[0][s]);
                float e1 = __expf(lp[1][s]);
                float e2 = __expf(lp[2][s]);
                float e3 = __expf(lp[3][s]);
                float tot = 1e-8f;
                tot += (wm & 1) ? e0 : 0.0f;
                tot += (wm & 2) ? e1 : 0.0f;
                tot += (wm & 4) ? e2 : 0.0f;
                tot += (wm & 8) ? e3 : 0.0f;
                float tll = (tm & 1) ? lp[0][s]
                          : (tm & 2) ? lp[1][s]
                          : (tm & 4) ? lp[2][s] : lp[3][s];
                float et  = (tm & 1) ? e0
                          : (tm & 2) ? e1
                          : (tm & 4) ? e2 : e3;
                acc += tll - __logf(tot + et);
            }
        }
    }

    // fp64 block reduction
    double dacc = (double)acc;
    #pragma unroll
    for (int off = 16; off > 0; off >>= 1)
        dacc += __shfl_down_sync(0xffffffffu, dacc, off);
    __shared__ double wsum[8];
    __shared__ unsigned int slast;
    int lane = threadIdx.x & 31;
    int w = threadIdx.x >> 5;
    if (lane == 0) wsum[w] = dacc;
    __syncthreads();
    if (w == 0) {
        int nwarp = blockDim.x >> 5;
        double b = (lane < nwarp) ? wsum[lane] : 0.0;
        #pragma unroll
        for (int off = 4; off > 0; off >>= 1)
            b += __shfl_down_sync(0xffffffffu, b, off);
        if (lane == 0) {
            atomicAdd(&g_sum, b);
            __threadfence();
            unsigned int t = atomicAdd(&g_ticket, 1u);
            slast = (t == gridDim.x - 1) ? 1u : 0u;
        }
    }
    __syncthreads();

    // Last block: tail samples + finalize + self-reset for graph replay.
    if (slast && threadIdx.x == 0) {
        double s = atomicAdd(&g_sum, 0.0);
        const int n0 = (N >> 2) << 2;
        for (int n = n0; n < N; ++n) {
            for (int i = 0; i < KC; ++i) {
                if (!sp.active[i]) continue;
                const float* base = pred + (size_t)i * D * N;
                float lp[KC];
                for (int j = 0; j < KC; ++j) {
                    float M = 0.f;
                    for (int r = 0; r < D; ++r) {
                        float sr = -sp.bias[j][r];
                        for (int c = 0; c <= r; ++c)
                            sr = fmaf(sp.Linv[j][r][c], base[(size_t)c * N + n], sr);
                        M = fmaf(sr, sr, M);
                    }
                    lp[j] = fmaf(0.5f, M, sp.cfix[j]);
                }
                int tm = sp.tmask[i], wm = sp.wmask[i];
                float tot = 1e-8f, tll = 0.f, et = 0.f;
                for (int j = 0; j < KC; ++j) {
                    if ((wm >> j) & 1) tot += __expf(lp[j]);
                    if ((tm >> j) & 1) { tll = lp[j]; et = __expf(lp[j]); }
                }
                s += (double)(tll - __logf(tot + et));
            }
        }
        int cnt = sp.cnt;
        float res = 0.0f;
        if (cnt > 0 && N > 0)
            res = (float)(-s / ((double)N * (double)cnt));
        out[0] = res;
        // reset accumulators for the next graph replay
        g_sum = 0.0;
        g_ticket = 0u;
        __threadfence();
    }
}

// ---------------------------------------------------------------------------
extern "C" void kernel_launch(void* const* d_in, const int* in_sizes, int n_in,
                              void* d_out, int out_size)
{
    const float* pred    = (const float*)d_in[0];  // (K, d, N)
    const float* means   = (const float*)d_in[1];  // (K, d)
    const float* covs    = (const float*)d_in[2];  // (K, d, d)
    const int*   indices = (const int*)d_in[3];    // (K,)

    const int N = in_sizes[0] / (KC * D);

    setup_kernel<<<1, 32>>>(means, covs, indices);

    const int N4 = N >> 2;
    const int threads = 256;
    int blocks = (N4 + threads - 1) / threads;
    if (blocks < 1) blocks = 1;
    lp_kernel<<<blocks, threads>>>(pred, N, (float*)d_out);
}